// round 8
// baseline (speedup 1.0000x reference)
#include <cuda_runtime.h>
#include <cstdint>

#define N_APP 100000
#define N_ATTR 50000
#define NE 500000
#define D 128

// ---------------- device scratch (allocation-free per rules) ----------------
__device__ __align__(16) float g_deg0[N_ATTR];
__device__ __align__(16) float g_deg1[N_APP];
__device__ __align__(16) float g_deg2[N_APP];
__device__ __align__(16) float g_sew0[NE];
__device__ __align__(16) float g_sew1[NE];
__device__ __align__(16) float g_sew2[NE];
__device__ __align__(16) float g_P0[(size_t)N_APP * D];
__device__ __align__(16) float g_P1[(size_t)N_ATTR * D];
__device__ __align__(16) float g_P2[(size_t)N_APP * D];
__device__ __align__(16) float g_Hattr[(size_t)N_ATTR * D];
__device__ __align__(16) float g_Happ[(size_t)N_APP * D];
__device__ __align__(16) float g_Wcomb[D * D];
__device__ __align__(16) float g_bcomb[D];
__device__ __align__(16) float g_A[D * 2];
__device__ __align__(16) float g_B1[D * 2];
__device__ __align__(16) float g_B2[D * 2];
__device__ __align__(16) float g_c2[2];
__device__ __align__(16) float g_Pattr[(size_t)N_ATTR * 2];
__device__ __align__(16) float g_QB2[(size_t)N_APP * 2];

// ---------------- small prep kernels ----------------
__global__ void zero_deg_kernel() {
    int i = blockIdx.x * blockDim.x + threadIdx.x;
    if (i < N_ATTR) g_deg0[i] = 0.f;
    if (i < N_APP) { g_deg1[i] = 0.f; g_deg2[i] = 0.f; }
}

__global__ void deg_kernel(const int* __restrict__ dst0,
                           const int* __restrict__ dst1,
                           const int* __restrict__ dst2) {
    int i = blockIdx.x * blockDim.x + threadIdx.x;
    if (i >= 3 * NE) return;
    if (i < NE)           atomicAdd(&g_deg0[dst0[i]], 1.f);
    else if (i < 2 * NE)  atomicAdd(&g_deg1[dst1[i - NE]], 1.f);
    else                  atomicAdd(&g_deg2[dst2[i - 2 * NE]], 1.f);
}

__global__ void sew_kernel(const float* __restrict__ ew0,
                           const float* __restrict__ ew1,
                           const float* __restrict__ ew2,
                           const int* __restrict__ dst0,
                           const int* __restrict__ dst1,
                           const int* __restrict__ dst2) {
    int i = blockIdx.x * blockDim.x + threadIdx.x;
    if (i >= 3 * NE) return;
    if (i < NE) {
        g_sew0[i] = ew0[i] / fmaxf(g_deg0[dst0[i]], 1.f);
    } else if (i < 2 * NE) {
        int e = i - NE;
        g_sew1[e] = ew1[e] / fmaxf(g_deg1[dst1[e]], 1.f);
    } else {
        int e = i - 2 * NE;
        g_sew2[e] = ew2[e] / fmaxf(g_deg2[dst2[e]], 1.f);
    }
}

__global__ void prep_kernel(const float* __restrict__ Wself1,
                            const float* __restrict__ b1,
                            const float* __restrict__ Wself2,
                            const float* __restrict__ Wneigh2,
                            const float* __restrict__ b2,
                            const float* __restrict__ Wc,
                            const float* __restrict__ bc) {
    int t = threadIdx.x;  // 256 threads
    for (int i = t; i < D * D; i += 256)
        g_Wcomb[i] = Wself1[D * D + i] + Wself1[2 * D * D + i];
    if (t < D) g_bcomb[t] = b1[D + t] + b1[2 * D + t];
    {
        int k = t >> 1, j = t & 1;
        float sA = 0.f, sB1 = 0.f, sB2 = 0.f;
        for (int x = 0; x < D; x++) {
            float wc = Wc[x * 2 + j];
            sA  += (Wself2[D * D + k * D + x] + Wself2[2 * D * D + k * D + x]) * wc;
            sB1 += Wneigh2[D * D + k * D + x] * wc;
            sB2 += Wneigh2[2 * D * D + k * D + x] * wc;
        }
        g_A[k * 2 + j] = sA;
        g_B1[k * 2 + j] = sB1;
        g_B2[k * 2 + j] = sB2;
    }
    if (t < 2) {
        float s = bc[t];
        for (int x = 0; x < D; x++)
            s += (b2[D + x] + b2[2 * D + x]) * Wc[x * 2 + t];
        g_c2[t] = s;
    }
}

// ---------------- fp32 GEMM with packed FFMA2 (fma.rn.f32x2) ----------------
// Y[M,128] = X[M,128] @ W[128,128] (+ bias). BM=64, 256 threads (16x16),
// per-thread 4 rows x 8 cols = 4 rows x 4 packed f32x2 pairs.
#define GEMM_BM 64
#define GEMM_PAD 132
#define GEMM_SMEM ((128 * GEMM_PAD + GEMM_BM * GEMM_PAD) * 4)

__device__ __forceinline__ unsigned long long pack2(float x, float y) {
    unsigned long long r;
    asm("mov.b64 %0, {%1, %2};" : "=l"(r) : "f"(x), "f"(y));
    return r;
}
__device__ __forceinline__ void unpack2(unsigned long long v, float& x, float& y) {
    asm("mov.b64 {%0, %1}, %2;" : "=f"(x), "=f"(y) : "l"(v));
}
__device__ __forceinline__ void ffma2(unsigned long long& d,
                                      unsigned long long a,
                                      unsigned long long b) {
    asm("fma.rn.f32x2 %0, %1, %2, %0;" : "+l"(d) : "l"(a), "l"(b));
}

__global__ void gemm_k128(const float* __restrict__ X, const float* __restrict__ W,
                          const float* __restrict__ bias, float* __restrict__ Y, int M) {
    extern __shared__ float sm[];
    float* Ws = sm;                       // [128][132]
    float* Xs = sm + 128 * GEMM_PAD;      // [64][132]
    int tid = threadIdx.x;
    int tx = tid & 15, ty = tid >> 4;
    int row0 = blockIdx.x * GEMM_BM;

    // load W (128x128) into padded smem
    for (int v = tid; v < 128 * 32; v += 256) {
        int r = v >> 5, c4 = v & 31;
        float4 w = ((const float4*)W)[r * 32 + c4];
        *(float4*)&Ws[r * GEMM_PAD + c4 * 4] = w;
    }
    // load X tile (64x128), zero-fill OOB rows
    for (int v = tid; v < GEMM_BM * 32; v += 256) {
        int r = v >> 5, c4 = v & 31;
        int row = row0 + r;
        float4 x = (row < M) ? ((const float4*)X)[(size_t)row * 32 + c4]
                             : make_float4(0.f, 0.f, 0.f, 0.f);
        *(float4*)&Xs[r * GEMM_PAD + c4 * 4] = x;
    }
    __syncthreads();

    // packed accumulators: 4 rows x 4 col-pairs (cols tx*8 .. tx*8+7)
    unsigned long long acc2[4][4];
#pragma unroll
    for (int r = 0; r < 4; r++)
#pragma unroll
        for (int p = 0; p < 4; p++) acc2[r][p] = 0ull;  // bit pattern = {+0.f,+0.f}

#pragma unroll 4
    for (int k = 0; k < 128; k++) {
        // B pairs: reinterpret 16B smem loads as two packed f32x2 each (free packing)
        const float* wrow = &Ws[k * GEMM_PAD + tx * 8];
        ulonglong2 b01 = *(const ulonglong2*)(wrow);      // {cols 0-1, cols 2-3}
        ulonglong2 b23 = *(const ulonglong2*)(wrow + 4);  // {cols 4-5, cols 6-7}
        unsigned long long bp[4] = {b01.x, b01.y, b23.x, b23.y};
        unsigned long long ap[4];
#pragma unroll
        for (int r = 0; r < 4; r++) {
            float a = Xs[(ty * 4 + r) * GEMM_PAD + k];
            ap[r] = pack2(a, a);
        }
#pragma unroll
        for (int r = 0; r < 4; r++)
#pragma unroll
            for (int p = 0; p < 4; p++) ffma2(acc2[r][p], ap[r], bp[p]);
    }

#pragma unroll
    for (int r = 0; r < 4; r++) {
        int row = row0 + ty * 4 + r;
        if (row < M) {
#pragma unroll
            for (int c4 = 0; c4 < 2; c4++) {
                int col = tx * 8 + c4 * 4;
                float4 o;
                unpack2(acc2[r][c4 * 2 + 0], o.x, o.y);
                unpack2(acc2[r][c4 * 2 + 1], o.z, o.w);
                if (bias) {
                    o.x += bias[col + 0]; o.y += bias[col + 1];
                    o.z += bias[col + 2]; o.w += bias[col + 3];
                }
                *(float4*)&Y[(size_t)row * 128 + col] = o;
            }
        }
    }
}

// ---------------- layer-1 scatter: warp/edge, 128-float message, v4 reductions ---------
__global__ void scatter_l1(const int* __restrict__ src0, const int* __restrict__ dst0,
                           const int* __restrict__ src1, const int* __restrict__ dst1,
                           const int* __restrict__ src2, const int* __restrict__ dst2) {
    int gw = (blockIdx.x * blockDim.x + threadIdx.x) >> 5;
    int lane = threadIdx.x & 31;
    if (gw >= 3 * NE) return;
    const int *src, *dst;
    const float *sew, *P;
    float* ACC;
    int e;
    if (gw < NE)          { e = gw;          src = src0; dst = dst0; sew = g_sew0; P = g_P0; ACC = g_Hattr; }
    else if (gw < 2 * NE) { e = gw - NE;     src = src1; dst = dst1; sew = g_sew1; P = g_P1; ACC = g_Happ; }
    else                  { e = gw - 2 * NE; src = src2; dst = dst2; sew = g_sew2; P = g_P2; ACC = g_Happ; }
    int s = src[e], d = dst[e];
    float w = sew[e];
    float4 v = ((const float4*)(P + (size_t)s * D))[lane];
    v.x *= w; v.y *= w; v.z *= w; v.w *= w;
    float* p = ACC + (size_t)d * D + lane * 4;
    asm volatile("red.global.add.v4.f32 [%0], {%1,%2,%3,%4};"
                 :: "l"(p), "f"(v.x), "f"(v.y), "f"(v.z), "f"(v.w) : "memory");
}

// ---------------- layer-2 projections (relu fused on load) ----------------
__global__ void proj_attr_kernel() {
    int gw = (blockIdx.x * blockDim.x + threadIdx.x) >> 5;
    int lane = threadIdx.x & 31;
    if (gw >= N_ATTR) return;
    float4 h = ((const float4*)(g_Hattr + (size_t)gw * D))[lane];
    h.x = fmaxf(h.x, 0.f); h.y = fmaxf(h.y, 0.f);
    h.z = fmaxf(h.z, 0.f); h.w = fmaxf(h.w, 0.f);
    int c0 = lane * 4;
    float s0 = h.x * g_B1[(c0 + 0) * 2] + h.y * g_B1[(c0 + 1) * 2] +
               h.z * g_B1[(c0 + 2) * 2] + h.w * g_B1[(c0 + 3) * 2];
    float s1 = h.x * g_B1[(c0 + 0) * 2 + 1] + h.y * g_B1[(c0 + 1) * 2 + 1] +
               h.z * g_B1[(c0 + 2) * 2 + 1] + h.w * g_B1[(c0 + 3) * 2 + 1];
#pragma unroll
    for (int o = 16; o; o >>= 1) {
        s0 += __shfl_xor_sync(0xFFFFFFFFu, s0, o);
        s1 += __shfl_xor_sync(0xFFFFFFFFu, s1, o);
    }
    if (lane == 0) { g_Pattr[gw * 2] = s0; g_Pattr[gw * 2 + 1] = s1; }
}

__global__ void proj_app_kernel(float* __restrict__ OUT) {
    int gw = (blockIdx.x * blockDim.x + threadIdx.x) >> 5;
    int lane = threadIdx.x & 31;
    if (gw >= N_APP) return;
    float4 h = ((const float4*)(g_Happ + (size_t)gw * D))[lane];
    h.x = fmaxf(h.x, 0.f); h.y = fmaxf(h.y, 0.f);
    h.z = fmaxf(h.z, 0.f); h.w = fmaxf(h.w, 0.f);
    int c0 = lane * 4;
    float a0 = h.x * g_A[(c0 + 0) * 2] + h.y * g_A[(c0 + 1) * 2] +
               h.z * g_A[(c0 + 2) * 2] + h.w * g_A[(c0 + 3) * 2];
    float a1 = h.x * g_A[(c0 + 0) * 2 + 1] + h.y * g_A[(c0 + 1) * 2 + 1] +
               h.z * g_A[(c0 + 2) * 2 + 1] + h.w * g_A[(c0 + 3) * 2 + 1];
    float b0 = h.x * g_B2[(c0 + 0) * 2] + h.y * g_B2[(c0 + 1) * 2] +
               h.z * g_B2[(c0 + 2) * 2] + h.w * g_B2[(c0 + 3) * 2];
    float b1 = h.x * g_B2[(c0 + 0) * 2 + 1] + h.y * g_B2[(c0 + 1) * 2 + 1] +
               h.z * g_B2[(c0 + 2) * 2 + 1] + h.w * g_B2[(c0 + 3) * 2 + 1];
#pragma unroll
    for (int o = 16; o; o >>= 1) {
        a0 += __shfl_xor_sync(0xFFFFFFFFu, a0, o);
        a1 += __shfl_xor_sync(0xFFFFFFFFu, a1, o);
        b0 += __shfl_xor_sync(0xFFFFFFFFu, b0, o);
        b1 += __shfl_xor_sync(0xFFFFFFFFu, b1, o);
    }
    if (lane == 0) {
        OUT[(size_t)gw * 2 + 0] = a0 + g_c2[0];
        OUT[(size_t)gw * 2 + 1] = a1 + g_c2[1];
        g_QB2[gw * 2 + 0] = b0;
        g_QB2[gw * 2 + 1] = b1;
    }
}

// ---------------- layer-2 scatter: 2 floats/edge, v2 reductions ----------------
__global__ void scatter_l2(const int* __restrict__ src1, const int* __restrict__ dst1,
                           const int* __restrict__ src2, const int* __restrict__ dst2,
                           float* __restrict__ OUT) {
    int i = blockIdx.x * blockDim.x + threadIdx.x;
    if (i >= 2 * NE) return;
    int s, d; float w; const float* Q;
    if (i < NE) { s = src1[i]; d = dst1[i]; w = g_sew1[i]; Q = g_Pattr; }
    else { int e = i - NE; s = src2[e]; d = dst2[e]; w = g_sew2[e]; Q = g_QB2; }
    float2 q = ((const float2*)Q)[s];
    float* p = OUT + (size_t)d * 2;
    asm volatile("red.global.add.v2.f32 [%0], {%1,%2};"
                 :: "l"(p), "f"(q.x * w), "f"(q.y * w) : "memory");
}

// ---------------- launch ----------------
extern "C" void kernel_launch(void* const* d_in, const int* in_sizes, int n_in,
                              void* d_out, int out_size) {
    const float* x_app   = (const float*)d_in[0];
    const float* x_attr  = (const float*)d_in[1];
    const float* ew0     = (const float*)d_in[2];
    const float* ew1     = (const float*)d_in[3];
    const float* ew2     = (const float*)d_in[4];
    const float* Wself1  = (const float*)d_in[5];
    const float* Wneigh1 = (const float*)d_in[6];
    const float* b1      = (const float*)d_in[7];
    const float* Wself2  = (const float*)d_in[8];
    const float* Wneigh2 = (const float*)d_in[9];
    const float* b2      = (const float*)d_in[10];
    const float* Wc      = (const float*)d_in[11];
    const float* bc      = (const float*)d_in[12];
    const int* src0 = (const int*)d_in[13];
    const int* dst0 = (const int*)d_in[14];
    const int* src1 = (const int*)d_in[15];
    const int* dst1 = (const int*)d_in[16];
    const int* src2 = (const int*)d_in[17];
    const int* dst2 = (const int*)d_in[18];
    float* OUT = (float*)d_out;

    float *pP0, *pP1, *pP2, *pHattr, *pHapp, *pWcomb, *pbcomb;
    cudaGetSymbolAddress((void**)&pP0, g_P0);
    cudaGetSymbolAddress((void**)&pP1, g_P1);
    cudaGetSymbolAddress((void**)&pP2, g_P2);
    cudaGetSymbolAddress((void**)&pHattr, g_Hattr);
    cudaGetSymbolAddress((void**)&pHapp, g_Happ);
    cudaGetSymbolAddress((void**)&pWcomb, g_Wcomb);
    cudaGetSymbolAddress((void**)&pbcomb, g_bcomb);

    cudaFuncSetAttribute(gemm_k128, cudaFuncAttributeMaxDynamicSharedMemorySize, GEMM_SMEM);

    prep_kernel<<<1, 256>>>(Wself1, b1, Wself2, Wneigh2, b2, Wc, bc);
    zero_deg_kernel<<<(N_APP + 255) / 256, 256>>>();
    deg_kernel<<<(3 * NE + 255) / 256, 256>>>(dst0, dst1, dst2);
    sew_kernel<<<(3 * NE + 255) / 256, 256>>>(ew0, ew1, ew2, dst0, dst1, dst2);

    gemm_k128<<<(N_ATTR + GEMM_BM - 1) / GEMM_BM, 256, GEMM_SMEM>>>(x_attr, Wself1, b1, pHattr, N_ATTR);
    gemm_k128<<<(N_APP + GEMM_BM - 1) / GEMM_BM, 256, GEMM_SMEM>>>(x_app, pWcomb, pbcomb, pHapp, N_APP);
    gemm_k128<<<(N_APP + GEMM_BM - 1) / GEMM_BM, 256, GEMM_SMEM>>>(x_app, Wneigh1, nullptr, pP0, N_APP);
    gemm_k128<<<(N_ATTR + GEMM_BM - 1) / GEMM_BM, 256, GEMM_SMEM>>>(x_attr, Wneigh1 + D * D, nullptr, pP1, N_ATTR);
    gemm_k128<<<(N_APP + GEMM_BM - 1) / GEMM_BM, 256, GEMM_SMEM>>>(x_app, Wneigh1 + 2 * D * D, nullptr, pP2, N_APP);

    scatter_l1<<<(3 * NE + 3) / 4, 128>>>(src0, dst0, src1, dst1, src2, dst2);

    proj_attr_kernel<<<(N_ATTR + 3) / 4, 128>>>();
    proj_app_kernel<<<(N_APP + 3) / 4, 128>>>(OUT);
    scatter_l2<<<(2 * NE + 255) / 256, 256>>>(src1, dst1, src2, dst2, OUT);
}

// round 10
// speedup vs baseline: 1.0043x; 1.0043x over previous
#include <cuda_runtime.h>
#include <cstdint>

#define N_APP 100000
#define N_ATTR 50000
#define NE 500000
#define D 128

// ---------------- device scratch (allocation-free per rules) ----------------
__device__ __align__(16) float g_deg0[N_ATTR];
__device__ __align__(16) float g_deg1[N_APP];
__device__ __align__(16) float g_deg2[N_APP];
__device__ __align__(16) float g_sew0[NE];
__device__ __align__(16) float g_sew1[NE];
__device__ __align__(16) float g_sew2[NE];
__device__ __align__(16) float g_P0[(size_t)N_APP * D];
__device__ __align__(16) float g_P1[(size_t)N_ATTR * D];
__device__ __align__(16) float g_P2[(size_t)N_APP * D];
__device__ __align__(16) float g_Hattr[(size_t)N_ATTR * D];
__device__ __align__(16) float g_Happ[(size_t)N_APP * D];
__device__ __align__(16) float g_Wcomb[D * D];
__device__ __align__(16) float g_bcomb[D];
__device__ __align__(16) float g_A[D * 2];
__device__ __align__(16) float g_B1[D * 2];
__device__ __align__(16) float g_B2[D * 2];
__device__ __align__(16) float g_c2[2];
__device__ __align__(16) float g_Pattr[(size_t)N_ATTR * 2];
__device__ __align__(16) float g_QB2[(size_t)N_APP * 2];

// ---------------- small prep kernels ----------------
__global__ void zero_deg_kernel() {
    int i = blockIdx.x * blockDim.x + threadIdx.x;
    if (i < N_ATTR) g_deg0[i] = 0.f;
    if (i < N_APP) { g_deg1[i] = 0.f; g_deg2[i] = 0.f; }
}

__global__ void deg_kernel(const int* __restrict__ dst0,
                           const int* __restrict__ dst1,
                           const int* __restrict__ dst2) {
    int i = blockIdx.x * blockDim.x + threadIdx.x;
    if (i >= 3 * NE) return;
    if (i < NE)           atomicAdd(&g_deg0[dst0[i]], 1.f);
    else if (i < 2 * NE)  atomicAdd(&g_deg1[dst1[i - NE]], 1.f);
    else                  atomicAdd(&g_deg2[dst2[i - 2 * NE]], 1.f);
}

__global__ void sew_kernel(const float* __restrict__ ew0,
                           const float* __restrict__ ew1,
                           const float* __restrict__ ew2,
                           const int* __restrict__ dst0,
                           const int* __restrict__ dst1,
                           const int* __restrict__ dst2) {
    int i = blockIdx.x * blockDim.x + threadIdx.x;
    if (i >= 3 * NE) return;
    if (i < NE) {
        g_sew0[i] = ew0[i] / fmaxf(g_deg0[dst0[i]], 1.f);
    } else if (i < 2 * NE) {
        int e = i - NE;
        g_sew1[e] = ew1[e] / fmaxf(g_deg1[dst1[e]], 1.f);
    } else {
        int e = i - 2 * NE;
        g_sew2[e] = ew2[e] / fmaxf(g_deg2[dst2[e]], 1.f);
    }
}

__global__ void prep_kernel(const float* __restrict__ Wself1,
                            const float* __restrict__ b1,
                            const float* __restrict__ Wself2,
                            const float* __restrict__ Wneigh2,
                            const float* __restrict__ b2,
                            const float* __restrict__ Wc,
                            const float* __restrict__ bc) {
    int t = threadIdx.x;  // 256 threads
    for (int i = t; i < D * D; i += 256)
        g_Wcomb[i] = Wself1[D * D + i] + Wself1[2 * D * D + i];
    if (t < D) g_bcomb[t] = b1[D + t] + b1[2 * D + t];
    {
        int k = t >> 1, j = t & 1;
        float sA = 0.f, sB1 = 0.f, sB2 = 0.f;
        for (int x = 0; x < D; x++) {
            float wc = Wc[x * 2 + j];
            sA  += (Wself2[D * D + k * D + x] + Wself2[2 * D * D + k * D + x]) * wc;
            sB1 += Wneigh2[D * D + k * D + x] * wc;
            sB2 += Wneigh2[2 * D * D + k * D + x] * wc;
        }
        g_A[k * 2 + j] = sA;
        g_B1[k * 2 + j] = sB1;
        g_B2[k * 2 + j] = sB2;
    }
    if (t < 2) {
        float s = bc[t];
        for (int x = 0; x < D; x++)
            s += (b2[D + x] + b2[2 * D + x]) * Wc[x * 2 + t];
        g_c2[t] = s;
    }
}

// ---------------- fp32 GEMM with packed FFMA2 (fma.rn.f32x2) ----------------
#define GEMM_BM 64
#define GEMM_PAD 132
#define GEMM_SMEM ((128 * GEMM_PAD + GEMM_BM * GEMM_PAD) * 4)

__device__ __forceinline__ unsigned long long pack2(float x, float y) {
    unsigned long long r;
    asm("mov.b64 %0, {%1, %2};" : "=l"(r) : "f"(x), "f"(y));
    return r;
}
__device__ __forceinline__ void unpack2(unsigned long long v, float& x, float& y) {
    asm("mov.b64 {%0, %1}, %2;" : "=f"(x), "=f"(y) : "l"(v));
}
__device__ __forceinline__ void ffma2(unsigned long long& d,
                                      unsigned long long a,
                                      unsigned long long b) {
    asm("fma.rn.f32x2 %0, %1, %2, %0;" : "+l"(d) : "l"(a), "l"(b));
}

__global__ void gemm_k128(const float* __restrict__ X, const float* __restrict__ W,
                          const float* __restrict__ bias, float* __restrict__ Y, int M) {
    extern __shared__ float sm[];
    float* Ws = sm;                       // [128][132]
    float* Xs = sm + 128 * GEMM_PAD;      // [64][132]
    int tid = threadIdx.x;
    int tx = tid & 15, ty = tid >> 4;
    int row0 = blockIdx.x * GEMM_BM;

    for (int v = tid; v < 128 * 32; v += 256) {
        int r = v >> 5, c4 = v & 31;
        float4 w = ((const float4*)W)[r * 32 + c4];
        *(float4*)&Ws[r * GEMM_PAD + c4 * 4] = w;
    }
    for (int v = tid; v < GEMM_BM * 32; v += 256) {
        int r = v >> 5, c4 = v & 31;
        int row = row0 + r;
        float4 x = (row < M) ? ((const float4*)X)[(size_t)row * 32 + c4]
                             : make_float4(0.f, 0.f, 0.f, 0.f);
        *(float4*)&Xs[r * GEMM_PAD + c4 * 4] = x;
    }
    __syncthreads();

    unsigned long long acc2[4][4];
#pragma unroll
    for (int r = 0; r < 4; r++)
#pragma unroll
        for (int p = 0; p < 4; p++) acc2[r][p] = 0ull;

#pragma unroll 4
    for (int k = 0; k < 128; k++) {
        const float* wrow = &Ws[k * GEMM_PAD + tx * 8];
        ulonglong2 b01 = *(const ulonglong2*)(wrow);
        ulonglong2 b23 = *(const ulonglong2*)(wrow + 4);
        unsigned long long bp[4] = {b01.x, b01.y, b23.x, b23.y};
        unsigned long long ap[4];
#pragma unroll
        for (int r = 0; r < 4; r++) {
            float a = Xs[(ty * 4 + r) * GEMM_PAD + k];
            ap[r] = pack2(a, a);
        }
#pragma unroll
        for (int r = 0; r < 4; r++)
#pragma unroll
            for (int p = 0; p < 4; p++) ffma2(acc2[r][p], ap[r], bp[p]);
    }

#pragma unroll
    for (int r = 0; r < 4; r++) {
        int row = row0 + ty * 4 + r;
        if (row < M) {
#pragma unroll
            for (int c4 = 0; c4 < 2; c4++) {
                int col = tx * 8 + c4 * 4;
                float4 o;
                unpack2(acc2[r][c4 * 2 + 0], o.x, o.y);
                unpack2(acc2[r][c4 * 2 + 1], o.z, o.w);
                if (bias) {
                    o.x += bias[col + 0]; o.y += bias[col + 1];
                    o.z += bias[col + 2]; o.w += bias[col + 3];
                }
                *(float4*)&Y[(size_t)row * 128 + col] = o;
            }
        }
    }
}

// ---------------- layer-1 scatter: one relation per launch (L2 locality) ---------
__global__ void scatter_rel(const int* __restrict__ src, const int* __restrict__ dst,
                            const float* __restrict__ sew, const float* __restrict__ P,
                            float* __restrict__ ACC) {
    int gw = (blockIdx.x * blockDim.x + threadIdx.x) >> 5;
    int lane = threadIdx.x & 31;
    if (gw >= NE) return;
    int s = src[gw], d = dst[gw];
    float w = sew[gw];
    float4 v = ((const float4*)(P + (size_t)s * D))[lane];
    v.x *= w; v.y *= w; v.z *= w; v.w *= w;
    float* p = ACC + (size_t)d * D + lane * 4;
    asm volatile("red.global.add.v4.f32 [%0], {%1,%2,%3,%4};"
                 :: "l"(p), "f"(v.x), "f"(v.y), "f"(v.z), "f"(v.w) : "memory");
}

// ---------------- layer-2 projections (relu fused on load) ----------------
__global__ void proj_attr_kernel() {
    int gw = (blockIdx.x * blockDim.x + threadIdx.x) >> 5;
    int lane = threadIdx.x & 31;
    if (gw >= N_ATTR) return;
    float4 h = ((const float4*)(g_Hattr + (size_t)gw * D))[lane];
    h.x = fmaxf(h.x, 0.f); h.y = fmaxf(h.y, 0.f);
    h.z = fmaxf(h.z, 0.f); h.w = fmaxf(h.w, 0.f);
    int c0 = lane * 4;
    float s0 = h.x * g_B1[(c0 + 0) * 2] + h.y * g_B1[(c0 + 1) * 2] +
               h.z * g_B1[(c0 + 2) * 2] + h.w * g_B1[(c0 + 3) * 2];
    float s1 = h.x * g_B1[(c0 + 0) * 2 + 1] + h.y * g_B1[(c0 + 1) * 2 + 1] +
               h.z * g_B1[(c0 + 2) * 2 + 1] + h.w * g_B1[(c0 + 3) * 2 + 1];
#pragma unroll
    for (int o = 16; o; o >>= 1) {
        s0 += __shfl_xor_sync(0xFFFFFFFFu, s0, o);
        s1 += __shfl_xor_sync(0xFFFFFFFFu, s1, o);
    }
    if (lane == 0) { g_Pattr[gw * 2] = s0; g_Pattr[gw * 2 + 1] = s1; }
}

__global__ void proj_app_kernel(float* __restrict__ OUT) {
    int gw = (blockIdx.x * blockDim.x + threadIdx.x) >> 5;
    int lane = threadIdx.x & 31;
    if (gw >= N_APP) return;
    float4 h = ((const float4*)(g_Happ + (size_t)gw * D))[lane];
    h.x = fmaxf(h.x, 0.f); h.y = fmaxf(h.y, 0.f);
    h.z = fmaxf(h.z, 0.f); h.w = fmaxf(h.w, 0.f);
    int c0 = lane * 4;
    float a0 = h.x * g_A[(c0 + 0) * 2] + h.y * g_A[(c0 + 1) * 2] +
               h.z * g_A[(c0 + 2) * 2] + h.w * g_A[(c0 + 3) * 2];
    float a1 = h.x * g_A[(c0 + 0) * 2 + 1] + h.y * g_A[(c0 + 1) * 2 + 1] +
               h.z * g_A[(c0 + 2) * 2 + 1] + h.w * g_A[(c0 + 3) * 2 + 1];
    float b0 = h.x * g_B2[(c0 + 0) * 2] + h.y * g_B2[(c0 + 1) * 2] +
               h.z * g_B2[(c0 + 2) * 2] + h.w * g_B2[(c0 + 3) * 2];
    float b1 = h.x * g_B2[(c0 + 0) * 2 + 1] + h.y * g_B2[(c0 + 1) * 2 + 1] +
               h.z * g_B2[(c0 + 2) * 2 + 1] + h.w * g_B2[(c0 + 3) * 2 + 1];
#pragma unroll
    for (int o = 16; o; o >>= 1) {
        a0 += __shfl_xor_sync(0xFFFFFFFFu, a0, o);
        a1 += __shfl_xor_sync(0xFFFFFFFFu, a1, o);
        b0 += __shfl_xor_sync(0xFFFFFFFFu, b0, o);
        b1 += __shfl_xor_sync(0xFFFFFFFFu, b1, o);
    }
    if (lane == 0) {
        OUT[(size_t)gw * 2 + 0] = a0 + g_c2[0];
        OUT[(size_t)gw * 2 + 1] = a1 + g_c2[1];
        g_QB2[gw * 2 + 0] = b0;
        g_QB2[gw * 2 + 1] = b1;
    }
}

// ---------------- layer-2 scatter: 2 floats/edge, v2 reductions ----------------
__global__ void scatter_l2(const int* __restrict__ src1, const int* __restrict__ dst1,
                           const int* __restrict__ src2, const int* __restrict__ dst2,
                           float* __restrict__ OUT) {
    int i = blockIdx.x * blockDim.x + threadIdx.x;
    if (i >= 2 * NE) return;
    int s, d; float w; const float* Q;
    if (i < NE) { s = src1[i]; d = dst1[i]; w = g_sew1[i]; Q = g_Pattr; }
    else { int e = i - NE; s = src2[e]; d = dst2[e]; w = g_sew2[e]; Q = g_QB2; }
    float2 q = ((const float2*)Q)[s];
    float* p = OUT + (size_t)d * 2;
    asm volatile("red.global.add.v2.f32 [%0], {%1,%2};"
                 :: "l"(p), "f"(q.x * w), "f"(q.y * w) : "memory");
}

// ---------------- launch ----------------
extern "C" void kernel_launch(void* const* d_in, const int* in_sizes, int n_in,
                              void* d_out, int out_size) {
    const float* x_app   = (const float*)d_in[0];
    const float* x_attr  = (const float*)d_in[1];
    const float* ew0     = (const float*)d_in[2];
    const float* ew1     = (const float*)d_in[3];
    const float* ew2     = (const float*)d_in[4];
    const float* Wself1  = (const float*)d_in[5];
    const float* Wneigh1 = (const float*)d_in[6];
    const float* b1      = (const float*)d_in[7];
    const float* Wself2  = (const float*)d_in[8];
    const float* Wneigh2 = (const float*)d_in[9];
    const float* b2      = (const float*)d_in[10];
    const float* Wc      = (const float*)d_in[11];
    const float* bc      = (const float*)d_in[12];
    const int* src0 = (const int*)d_in[13];
    const int* dst0 = (const int*)d_in[14];
    const int* src1 = (const int*)d_in[15];
    const int* dst1 = (const int*)d_in[16];
    const int* src2 = (const int*)d_in[17];
    const int* dst2 = (const int*)d_in[18];
    float* OUT = (float*)d_out;

    float *pP0, *pP1, *pP2, *pHattr, *pHapp, *pWcomb, *pbcomb;
    float *psew0, *psew1, *psew2;
    cudaGetSymbolAddress((void**)&pP0, g_P0);
    cudaGetSymbolAddress((void**)&pP1, g_P1);
    cudaGetSymbolAddress((void**)&pP2, g_P2);
    cudaGetSymbolAddress((void**)&pHattr, g_Hattr);
    cudaGetSymbolAddress((void**)&pHapp, g_Happ);
    cudaGetSymbolAddress((void**)&pWcomb, g_Wcomb);
    cudaGetSymbolAddress((void**)&pbcomb, g_bcomb);
    cudaGetSymbolAddress((void**)&psew0, g_sew0);
    cudaGetSymbolAddress((void**)&psew1, g_sew1);
    cudaGetSymbolAddress((void**)&psew2, g_sew2);

    cudaFuncSetAttribute(gemm_k128, cudaFuncAttributeMaxDynamicSharedMemorySize, GEMM_SMEM);

    // launch order chosen so the ncu capture window (my 4th launch) hits a
    // representative 100k-row GEMM instead of a prep kernel.
    prep_kernel<<<1, 256>>>(Wself1, b1, Wself2, Wneigh2, b2, Wc, bc);
    zero_deg_kernel<<<(N_APP + 255) / 256, 256>>>();

    gemm_k128<<<(N_ATTR + GEMM_BM - 1) / GEMM_BM, 256, GEMM_SMEM>>>(x_attr, Wself1, b1, pHattr, N_ATTR);
    gemm_k128<<<(N_APP + GEMM_BM - 1) / GEMM_BM, 256, GEMM_SMEM>>>(x_app, pWcomb, pbcomb, pHapp, N_APP);
    gemm_k128<<<(N_APP + GEMM_BM - 1) / GEMM_BM, 256, GEMM_SMEM>>>(x_app, Wneigh1, nullptr, pP0, N_APP);
    gemm_k128<<<(N_ATTR + GEMM_BM - 1) / GEMM_BM, 256, GEMM_SMEM>>>(x_attr, Wneigh1 + D * D, nullptr, pP1, N_ATTR);
    gemm_k128<<<(N_APP + GEMM_BM - 1) / GEMM_BM, 256, GEMM_SMEM>>>(x_app, Wneigh1 + 2 * D * D, nullptr, pP2, N_APP);

    deg_kernel<<<(3 * NE + 255) / 256, 256>>>(dst0, dst1, dst2);
    sew_kernel<<<(3 * NE + 255) / 256, 256>>>(ew0, ew1, ew2, dst0, dst1, dst2);

    // per-relation scatters: each phase's working set (P + ACC) fits in L2
    scatter_rel<<<(NE + 7) / 8, 256>>>(src0, dst0, psew0, pP0, pHattr);
    scatter_rel<<<(NE + 7) / 8, 256>>>(src1, dst1, psew1, pP1, pHapp);
    scatter_rel<<<(NE + 7) / 8, 256>>>(src2, dst2, psew2, pP2, pHapp);

    proj_attr_kernel<<<(N_ATTR + 3) / 4, 128>>>();
    proj_app_kernel<<<(N_APP + 3) / 4, 128>>>(OUT);
    scatter_l2<<<(2 * NE + 255) / 256, 256>>>(src1, dst1, src2, dst2, OUT);
}